// round 15
// baseline (speedup 1.0000x reference)
#include <cuda_runtime.h>
#include <cuda_fp16.h>
#include <math.h>
#include <stdint.h>

#define BB 4
#define NQ 1024
#define HW 4096
#define CC 1024
#define HH 8
#define DH 128

typedef __half f16;

// ---------------- scratch (device globals; no allocations allowed) ----------
__device__ f16 s_qin_h[(size_t)BB * NQ * CC];
__device__ f16 s_mem_h[(size_t)BB * HW * CC];
__device__ f16 s_wq_h[(size_t)CC * CC];
__device__ f16 s_wk_h[(size_t)CC * CC];
__device__ f16 s_wv_h[(size_t)CC * CC];
__device__ f16 s_wo_h[(size_t)CC * CC];
__device__ f16 s_q_h[(size_t)BB * NQ * CC];
__device__ f16 s_k_h[(size_t)BB * HW * CC];
__device__ f16 s_v_h[(size_t)BB * HW * CC];
__device__ f16 s_a_h[(size_t)BB * NQ * CC];
__device__ uint32_t s_mbits[(size_t)BB * NQ * HW / 32];

// ============================ helpers =======================================
__device__ __forceinline__ uint32_t smem_u32(const void* p) {
    uint32_t a;
    asm("{ .reg .u64 t; cvta.to.shared.u64 t, %1; cvt.u32.u64 %0, t; }"
        : "=r"(a) : "l"(p));
    return a;
}

__device__ __forceinline__ void ldx4(uint32_t* r, uint32_t addr) {
    asm volatile("ldmatrix.sync.aligned.m8n8.x4.shared.b16 {%0,%1,%2,%3}, [%4];"
                 : "=r"(r[0]), "=r"(r[1]), "=r"(r[2]), "=r"(r[3]) : "r"(addr));
}

__device__ __forceinline__ void ldx4t(uint32_t* r, uint32_t addr) {
    asm volatile("ldmatrix.sync.aligned.m8n8.x4.trans.shared.b16 {%0,%1,%2,%3}, [%4];"
                 : "=r"(r[0]), "=r"(r[1]), "=r"(r[2]), "=r"(r[3]) : "r"(addr));
}

__device__ __forceinline__ void mma_f16(float* c, const uint32_t* a,
                                        uint32_t b0, uint32_t b1) {
    asm volatile(
        "mma.sync.aligned.m16n8k16.row.col.f32.f16.f16.f32 "
        "{%0,%1,%2,%3}, {%4,%5,%6,%7}, {%8,%9}, {%0,%1,%2,%3};"
        : "+f"(c[0]), "+f"(c[1]), "+f"(c[2]), "+f"(c[3])
        : "r"(a[0]), "r"(a[1]), "r"(a[2]), "r"(a[3]), "r"(b0), "r"(b1));
}

__device__ __forceinline__ void cpa16(uint32_t dst, const void* src) {
    asm volatile("cp.async.cg.shared.global [%0], [%1], 16;"
                 :: "r"(dst), "l"(src) : "memory");
}
#define CP_COMMIT() asm volatile("cp.async.commit_group;" ::: "memory")
#define CP_WAIT0()  asm volatile("cp.async.wait_group 0;" ::: "memory")
#define CP_WAIT1()  asm volatile("cp.async.wait_group 1;" ::: "memory")

__device__ __forceinline__ uint32_t packh_hi(float x, float y) {
    __half2 h = __floats2half2_rn(x, y);
    return *(uint32_t*)&h;
}

__device__ __forceinline__ float ex2f(float x) {
    float y;
    asm("ex2.approx.ftz.f32 %0, %1;" : "=f"(y) : "f"(x));
    return y;
}

__device__ __forceinline__ uint32_t swz(int row, int chunk) {
    return (uint32_t)(row * 256 + ((chunk ^ (row & 7)) << 4));
}
__device__ __forceinline__ uint32_t swz128(int row, int chunk) {
    return (uint32_t)(row * 128 + ((chunk ^ (row & 7)) << 4));
}

// ============================================================================
// prep kernels (unchanged)
// ============================================================================
#define N4P_Q (BB * NQ * CC / 8)
#define N4P_M (BB * HW * CC / 8)
#define N4P_W (CC * CC / 8)
#define N4P_TOTAL (N4P_Q + N4P_M + 4 * N4P_W)

__global__ __launch_bounds__(256)
void round_all(const float* __restrict__ q,  f16* __restrict__ qo,
               const float* __restrict__ m,  f16* __restrict__ mo,
               const float* __restrict__ w0, f16* __restrict__ o0,
               const float* __restrict__ w1, f16* __restrict__ o1,
               const float* __restrict__ w2, f16* __restrict__ o2,
               const float* __restrict__ w3, f16* __restrict__ o3)
{
    size_t p = (size_t)blockIdx.x * blockDim.x + threadIdx.x;
    if (p >= (size_t)N4P_TOTAL) return;
    const float* x;
    f16* y;
    size_t off;
    if (p < N4P_Q) {
        x = q; y = qo; off = p;
    } else if (p < (size_t)N4P_Q + N4P_M) {
        x = m; y = mo; off = p - N4P_Q;
    } else {
        size_t r = p - N4P_Q - N4P_M;
        int ws = (int)(r / N4P_W);
        off = r % N4P_W;
        x = (ws == 0) ? w0 : (ws == 1) ? w1 : (ws == 2) ? w2 : w3;
        y = (ws == 0) ? o0 : (ws == 1) ? o1 : (ws == 2) ? o2 : o3;
    }
    const size_t i = off * 2;
    float4 v0 = ((const float4*)x)[i];
    float4 v1 = ((const float4*)x)[i + 1];
    __half2 a0 = __floats2half2_rn(v0.x, v0.y);
    __half2 a1 = __floats2half2_rn(v0.z, v0.w);
    __half2 a2 = __floats2half2_rn(v1.x, v1.y);
    __half2 a3 = __floats2half2_rn(v1.z, v1.w);
    ((uint4*)y)[off] = make_uint4(*(uint32_t*)&a0, *(uint32_t*)&a1,
                                  *(uint32_t*)&a2, *(uint32_t*)&a3);
}

__global__ __launch_bounds__(256)
void mask_bits(const float* __restrict__ m, uint32_t* __restrict__ out, int nwords)
{
    int w = blockIdx.x * blockDim.x + threadIdx.x;
    if (w >= nwords) return;
    const float4* p = (const float4*)(m + (size_t)w * 32);
    float4 v[8];
#pragma unroll
    for (int j = 0; j < 8; j++) v[j] = p[j];
    uint32_t bits = 0;
#pragma unroll
    for (int j = 0; j < 8; j++) {
        bits |= (v[j].x >= 0.5f ? (1u << (j * 4 + 0)) : 0u);
        bits |= (v[j].y >= 0.5f ? (1u << (j * 4 + 1)) : 0u);
        bits |= (v[j].z >= 0.5f ? (1u << (j * 4 + 2)) : 0u);
        bits |= (v[j].w >= 0.5f ? (1u << (j * 4 + 3)) : 0u);
    }
    out[w] = bits;
}

// ============================================================================
// GEMM v3 (unchanged from R14 — at the mma.sync ceiling)
// ============================================================================
#define GSTG 32768
#define GEMM_SMEM (3 * GSTG)
#define GNS (CC / 64)

__global__ __launch_bounds__(512, 2)
void gemm_f16(const f16* __restrict__ A, const f16* __restrict__ B,
              const float* __restrict__ bias,
              float* __restrict__ Yf, f16* __restrict__ Yh, float scale)
{
    extern __shared__ char sm[];
    const uint32_t sb = smem_u32(sm);

    const int tid  = threadIdx.x;
    const int wid  = tid >> 5;
    const int lane = tid & 31;
    const int wm = wid & 3;
    const int wn = wid >> 2;
    const int m0 = blockIdx.y * 128;
    const int n0 = blockIdx.x * 128;

    const int lrow = tid >> 2;
    const int lcb  = (tid & 3) * 2;

    const f16* Ap = A + (size_t)(m0 + lrow) * CC;
    const f16* Bp = B + (size_t)(n0 + lrow) * CC;

    float acc[2][4][4];
#pragma unroll
    for (int i = 0; i < 2; i++)
#pragma unroll
        for (int j = 0; j < 4; j++)
#pragma unroll
            for (int k = 0; k < 4; k++) acc[i][j][k] = 0.f;

    const int krow_in = ((lane >> 4) & 1) * 8 + (lane & 7);
    const int kc      = (lane >> 3) & 1;
    const int arow    = wm * 32 + (lane & 15);
    const int ac      = lane >> 4;

    auto issue = [&](int s) {
        const uint32_t stb = sb + (uint32_t)((s % 3) * GSTG);
        const int ko = s * 64;
#pragma unroll
        for (int c = 0; c < 2; c++) {
            const int ch = lcb + c;
            const uint32_t so = swz128(lrow, ch);
            cpa16(stb + so,         Ap + ko + ch * 8);
            cpa16(stb + 16384 + so, Bp + ko + ch * 8);
        }
    };

    issue(0); CP_COMMIT();
    issue(1); CP_COMMIT();

    for (int s = 0; s < GNS; s++) {
        CP_WAIT1();
        __syncthreads();
        if (s + 2 < GNS) issue(s + 2);
        CP_COMMIT();

        const uint32_t stb = sb + (uint32_t)((s % 3) * GSTG);
#pragma unroll
        for (int kt = 0; kt < 4; kt++) {
            uint32_t a_[2][4];
#pragma unroll
            for (int mt = 0; mt < 2; mt++)
                ldx4(a_[mt], stb + swz128(arow + mt * 16, 2 * kt + ac));
            uint32_t b_[2][4];
#pragma unroll
            for (int nh = 0; nh < 2; nh++)
                ldx4(b_[nh], stb + 16384 +
                             swz128(wn * 32 + nh * 16 + krow_in, 2 * kt + kc));
#pragma unroll
            for (int mt = 0; mt < 2; mt++) {
#pragma unroll
                for (int nh = 0; nh < 2; nh++) {
                    mma_f16(acc[mt][2 * nh + 0], a_[mt], b_[nh][0], b_[nh][1]);
                    mma_f16(acc[mt][2 * nh + 1], a_[mt], b_[nh][2], b_[nh][3]);
                }
            }
        }
    }

#pragma unroll
    for (int mt = 0; mt < 2; mt++) {
        const int r0 = m0 + wm * 32 + mt * 16 + (lane >> 2);
#pragma unroll
        for (int nt = 0; nt < 4; nt++) {
            const int c = n0 + wn * 32 + nt * 8 + (lane & 3) * 2;
            float2 bv = *(const float2*)(bias + c);
            float y00 = acc[mt][nt][0] + bv.x;
            float y01 = acc[mt][nt][1] + bv.y;
            float y10 = acc[mt][nt][2] + bv.x;
            float y11 = acc[mt][nt][3] + bv.y;
            if (Yf) {
                *(float2*)(Yf + (size_t)r0 * CC + c)       = make_float2(y00, y01);
                *(float2*)(Yf + (size_t)(r0 + 8) * CC + c) = make_float2(y10, y11);
            } else {
                y00 *= scale; y01 *= scale; y10 *= scale; y11 *= scale;
                *(uint32_t*)(Yh + (size_t)r0 * CC + c)       = packh_hi(y00, y01);
                *(uint32_t*)(Yh + (size_t)(r0 + 8) * CC + c) = packh_hi(y10, y11);
            }
        }
    }
}

// ============================================================================
// Flash v8: 2 CTAs/SM + deferred-PV. Split rings: Q 32KB resident,
// K ring 2x16KB, V ring 3x16KB (V_{i-1} survives issue(i+1)) = 112KB/CTA.
// Tile i: QK(i) MMAs -> PV(i-1) MMAs -> softmax(i) hidden under PV -> pack P_i.
// O-update order identical to in-order version (bit-exact).
// ============================================================================
#define QRGN  32768
#define KRB   QRGN            // K ring base
#define VRB   (QRGN + 32768)  // V ring base
#define TSTG  16384
#define FLASH_SMEM (QRGN + 2 * TSTG + 3 * TSTG)   // 114688
#define NKV (HW / 64)

__global__ __launch_bounds__(256, 2)
void flash_attn_tc8(const f16* __restrict__ Qh,
                    const f16* __restrict__ Kh, const f16* __restrict__ Vh,
                    const uint32_t* __restrict__ Mb, f16* __restrict__ Oh)
{
    extern __shared__ char sm[];
    const uint32_t sb = smem_u32(sm);

    const int tid  = threadIdx.x;
    const int wid  = tid >> 5;
    const int lane = tid & 31;
    const int q0 = blockIdx.x * 128;
    const int h  = blockIdx.y;
    const int b  = blockIdx.z;

    // ---- stage Q into resident region ----
    {
        const int row = tid >> 1;
        const int cb  = (tid & 1) * 8;
        const f16* qsrc = Qh + (size_t)(b * NQ + q0 + row) * CC + h * DH;
#pragma unroll
        for (int c = 0; c < 8; c++) {
            const int ch = cb + c;
            cpa16(sb + swz(row, ch), qsrc + ch * 8);
        }
        CP_COMMIT();
    }

    const int qrow = 16 * wid + (lane & 15);
    const int qc   = lane >> 4;

    const int krow_in = ((lane >> 4) & 1) * 8 + (lane & 7);
    const int kc      = (lane >> 3) & 1;
    const int vrow_in = (lane & 7) + ((lane >> 3) & 1) * 8;
    const int vc      = lane >> 4;

    const int kvrow = tid >> 2;
    const int kvcb  = (tid & 3) * 4;

    const f16* khb = Kh + (size_t)(b * HW + kvrow) * CC + h * DH;
    const f16* vhb = Vh + (size_t)(b * HW + kvrow) * CC + h * DH;

    const int r0l = 16 * wid + (lane >> 2);
    const int mc0 = 2 * (lane & 3);
    const uint32_t* mrow0 = Mb + (size_t)(b * NQ + q0 + r0l) * (HW / 32);
    const uint32_t* mrow1 = mrow0 + (size_t)8 * (HW / 32);

    auto issue = [&](int i) {
        const uint32_t kb = sb + KRB + (uint32_t)((i & 1) * TSTG);
        const uint32_t vb = sb + VRB + (uint32_t)((i % 3) * TSTG);
        const size_t koff = (size_t)(i * 64) * CC;
#pragma unroll
        for (int c = 0; c < 4; c++) {
            const int ch = kvcb + c;
            const uint32_t so = swz(kvrow, ch);
            cpa16(kb + so, khb + koff + ch * 8);
            cpa16(vb + so, vhb + koff + ch * 8);
        }
    };

    float m0r = -1e30f, m1r = -1e30f, l0r = 0.f, l1r = 0.f;
    float oc[16][4];
#pragma unroll
    for (int n = 0; n < 16; n++)
#pragma unroll
        for (int j = 0; j < 4; j++) oc[n][j] = 0.f;

    uint32_t pah[4][4];       // P_{i-1} fragments carried across iterations

    issue(0); CP_COMMIT();

    for (int i = 0; i < NKV; i++) {
        CP_WAIT0();           // Q + K_i + V_i complete
        __syncthreads();      // all warps done with K_{i-1}, V_{i-2} slots
        if (i + 1 < NKV) issue(i + 1);
        CP_COMMIT();

        const uint32_t kb  = sb + KRB + (uint32_t)((i & 1) * TSTG);
        const uint32_t vbp = sb + VRB + (uint32_t)(((i + 2) % 3) * TSTG);  // V_{i-1}

        const uint2 w0 = *(const uint2*)(mrow0 + i * 2);
        const uint2 w1 = *(const uint2*)(mrow1 + i * 2);

        // ---- 1) S_i = Q K_i^T ----
        float sc[8][4];
#pragma unroll
        for (int n = 0; n < 8; n++)
#pragma unroll
            for (int j = 0; j < 4; j++) sc[n][j] = 0.f;

#pragma unroll
        for (int kt = 0; kt < 8; kt++) {
            uint32_t qh_[4];
            ldx4(qh_, sb + swz(qrow, 2 * kt + qc));
#pragma unroll
            for (int j = 0; j < 4; j++) {
                uint32_t kh_[4];
                ldx4(kh_, kb + swz(16 * j + krow_in, 2 * kt + kc));
                mma_f16(sc[2 * j + 0], qh_, kh_[0], kh_[1]);
                mma_f16(sc[2 * j + 1], qh_, kh_[2], kh_[3]);
            }
        }

        // ---- 2) O += P_{i-1} V_{i-1} (tensor work covering softmax below) ----
        if (i > 0) {
#pragma unroll
            for (int kt = 0; kt < 4; kt++) {
#pragma unroll
                for (int np = 0; np < 8; np++) {
                    uint32_t v_[4];
                    ldx4t(v_, vbp + swz(16 * kt + vrow_in, 2 * np + vc));
                    mma_f16(oc[2 * np + 0], pah[kt], v_[0], v_[1]);
                    mma_f16(oc[2 * np + 1], pah[kt], v_[2], v_[3]);
                }
            }
        }

        // ---- 3) mask + online softmax (base-2) ----
        float mx0 = m0r, mx1 = m1r;
#pragma unroll
        for (int n = 0; n < 8; n++) {
            const uint32_t wa = (n < 4) ? w0.x : w0.y;
            const uint32_t wb = (n < 4) ? w1.x : w1.y;
            const int pos = (n & 3) * 8 + mc0;
            sc[n][0] = ((wa >> pos) & 1u)       ? sc[n][0] : -1e30f;
            sc[n][1] = ((wa >> (pos + 1)) & 1u) ? sc[n][1] : -1e30f;
            sc[n][2] = ((wb >> pos) & 1u)       ? sc[n][2] : -1e30f;
            sc[n][3] = ((wb >> (pos + 1)) & 1u) ? sc[n][3] : -1e30f;
            mx0 = fmaxf(mx0, fmaxf(sc[n][0], sc[n][1]));
            mx1 = fmaxf(mx1, fmaxf(sc[n][2], sc[n][3]));
        }
        mx0 = fmaxf(mx0, __shfl_xor_sync(0xffffffffu, mx0, 1));
        mx0 = fmaxf(mx0, __shfl_xor_sync(0xffffffffu, mx0, 2));
        mx1 = fmaxf(mx1, __shfl_xor_sync(0xffffffffu, mx1, 1));
        mx1 = fmaxf(mx1, __shfl_xor_sync(0xffffffffu, mx1, 2));

        const float alpha0 = ex2f(m0r - mx0);
        const float alpha1 = ex2f(m1r - mx1);
        m0r = mx0; m1r = mx1;

        float rs0 = 0.f, rs1 = 0.f;
#pragma unroll
        for (int n = 0; n < 8; n++) {
            sc[n][0] = ex2f(sc[n][0] - mx0);
            sc[n][1] = ex2f(sc[n][1] - mx0);
            sc[n][2] = ex2f(sc[n][2] - mx1);
            sc[n][3] = ex2f(sc[n][3] - mx1);
            rs0 += sc[n][0] + sc[n][1];
            rs1 += sc[n][2] + sc[n][3];
        }
        rs0 += __shfl_xor_sync(0xffffffffu, rs0, 1);
        rs0 += __shfl_xor_sync(0xffffffffu, rs0, 2);
        rs1 += __shfl_xor_sync(0xffffffffu, rs1, 1);
        rs1 += __shfl_xor_sync(0xffffffffu, rs1, 2);
        l0r = l0r * alpha0 + rs0;
        l1r = l1r * alpha1 + rs1;

        // ---- 4) O *= alpha_i (after PV_{i-1} adds) ----
#pragma unroll
        for (int n = 0; n < 16; n++) {
            oc[n][0] *= alpha0; oc[n][1] *= alpha0;
            oc[n][2] *= alpha1; oc[n][3] *= alpha1;
        }

        // ---- 5) pack P_i for next iteration ----
#pragma unroll
        for (int kt = 0; kt < 4; kt++) {
            pah[kt][0] = packh_hi(sc[2 * kt][0],     sc[2 * kt][1]);
            pah[kt][1] = packh_hi(sc[2 * kt][2],     sc[2 * kt][3]);
            pah[kt][2] = packh_hi(sc[2 * kt + 1][0], sc[2 * kt + 1][1]);
            pah[kt][3] = packh_hi(sc[2 * kt + 1][2], sc[2 * kt + 1][3]);
        }
    }

    // ---- tail: O += P_{last} V_{last} ----
    {
        const uint32_t vbl = sb + VRB + (uint32_t)(((NKV - 1) % 3) * TSTG);
#pragma unroll
        for (int kt = 0; kt < 4; kt++) {
#pragma unroll
            for (int np = 0; np < 8; np++) {
                uint32_t v_[4];
                ldx4t(v_, vbl + swz(16 * kt + vrow_in, 2 * np + vc));
                mma_f16(oc[2 * np + 0], pah[kt], v_[0], v_[1]);
                mma_f16(oc[2 * np + 1], pah[kt], v_[2], v_[3]);
            }
        }
    }

    // ---- normalize, write fp16 ----
    const float rl0 = 1.0f / l0r;
    const float rl1 = 1.0f / l1r;
    const size_t rbase0 = (size_t)(b * NQ + q0 + r0l) * CC + h * DH;
    const size_t rbase1 = rbase0 + (size_t)8 * CC;
#pragma unroll
    for (int n = 0; n < 16; n++) {
        const int c = n * 8 + mc0;
        *(uint32_t*)(Oh + rbase0 + c) = packh_hi(oc[n][0] * rl0, oc[n][1] * rl0);
        *(uint32_t*)(Oh + rbase1 + c) = packh_hi(oc[n][2] * rl1, oc[n][3] * rl1);
    }
}

// ---------------------------------------------------------------------------
extern "C" void kernel_launch(void* const* d_in, const int* in_sizes, int n_in,
                              void* d_out, int out_size)
{
    const float* query  = (const float*)d_in[0];
    const float* memory = (const float*)d_in[1];
    const float* mask   = (const float*)d_in[2];
    const float* Wq = (const float*)d_in[3];
    const float* bq = (const float*)d_in[4];
    const float* Wk = (const float*)d_in[5];
    const float* bk = (const float*)d_in[6];
    const float* Wv = (const float*)d_in[7];
    const float* bv = (const float*)d_in[8];
    const float* Wo = (const float*)d_in[9];
    const float* bo = (const float*)d_in[10];
    float* out = (float*)d_out;

    f16 *qin_h, *mem_h, *wq_h, *wk_h, *wv_h, *wo_h;
    f16 *q_h, *k_h, *v_h, *a_h;
    uint32_t* mb;
    cudaGetSymbolAddress((void**)&qin_h, s_qin_h);
    cudaGetSymbolAddress((void**)&mem_h, s_mem_h);
    cudaGetSymbolAddress((void**)&wq_h, s_wq_h);
    cudaGetSymbolAddress((void**)&wk_h, s_wk_h);
    cudaGetSymbolAddress((void**)&wv_h, s_wv_h);
    cudaGetSymbolAddress((void**)&wo_h, s_wo_h);
    cudaGetSymbolAddress((void**)&q_h, s_q_h);
    cudaGetSymbolAddress((void**)&k_h, s_k_h);
    cudaGetSymbolAddress((void**)&v_h, s_v_h);
    cudaGetSymbolAddress((void**)&a_h, s_a_h);
    cudaGetSymbolAddress((void**)&mb, s_mbits);

    cudaFuncSetAttribute(gemm_f16,
                         cudaFuncAttributeMaxDynamicSharedMemorySize, GEMM_SMEM);
    cudaFuncSetAttribute(flash_attn_tc8,
                         cudaFuncAttributeMaxDynamicSharedMemorySize, FLASH_SMEM);

    static cudaStream_t s2 = nullptr;
    static cudaEvent_t ev_fork = nullptr, ev_join = nullptr;
    if (!s2) {
        cudaStreamCreateWithFlags(&s2, cudaStreamNonBlocking);
        cudaEventCreateWithFlags(&ev_fork, cudaEventDisableTiming);
        cudaEventCreateWithFlags(&ev_join, cudaEventDisableTiming);
    }

    dim3 blk(256);
    dim3 blk512(512);
    const float scale = 0.08838834764831845f * 1.4426950408889634f;

    // ---- fork: mask_bits on side stream ----
    cudaEventRecord(ev_fork, 0);
    cudaStreamWaitEvent(s2, ev_fork, 0);
    {
        const int nwords = BB * NQ * HW / 32;
        mask_bits<<<(nwords + 255) / 256, blk, 0, s2>>>(mask, mb, nwords);
    }
    cudaEventRecord(ev_join, s2);

    // ---- fused rounds ----
    round_all<<<(N4P_TOTAL + 255) / 256, blk>>>(
        query, qin_h, memory, mem_h,
        Wq, wq_h, Wk, wk_h, Wv, wv_h, Wo, wo_h);

    // ---- projections ----
    gemm_f16<<<dim3(CC / 128, (BB * NQ) / 128), blk512, GEMM_SMEM>>>(
        qin_h, wq_h, bq, nullptr, q_h, scale);
    gemm_f16<<<dim3(CC / 128, (BB * HW) / 128), blk512, GEMM_SMEM>>>(
        mem_h, wk_h, bk, nullptr, k_h, 1.0f);
    gemm_f16<<<dim3(CC / 128, (BB * HW) / 128), blk512, GEMM_SMEM>>>(
        mem_h, wv_h, bv, nullptr, v_h, 1.0f);

    // ---- join: mask bitmap ready before flash ----
    cudaStreamWaitEvent(0, ev_join, 0);

    // ---- attention (deferred-PV, 2 CTAs/SM) ----
    flash_attn_tc8<<<dim3(NQ / 128, HH, BB), blk, FLASH_SMEM>>>(
        q_h, k_h, v_h, mb, a_h);

    // ---- output projection ----
    gemm_f16<<<dim3(CC / 128, (BB * NQ) / 128), blk512, GEMM_SMEM>>>(
        a_h, wo_h, bo, out, nullptr, 1.0f);
}

// round 16
// speedup vs baseline: 1.0885x; 1.0885x over previous
#include <cuda_runtime.h>
#include <cuda_fp16.h>
#include <math.h>
#include <stdint.h>

#define BB 4
#define NQ 1024
#define HW 4096
#define CC 1024
#define HH 8
#define DH 128

typedef __half f16;

// ---------------- scratch (device globals; no allocations allowed) ----------
__device__ f16 s_qin_h[(size_t)BB * NQ * CC];
__device__ f16 s_mem_h[(size_t)BB * HW * CC];
__device__ f16 s_wq_h[(size_t)CC * CC];
__device__ f16 s_wk_h[(size_t)CC * CC];
__device__ f16 s_wv_h[(size_t)CC * CC];
__device__ f16 s_wo_h[(size_t)CC * CC];
__device__ f16 s_q_h[(size_t)BB * NQ * CC];
__device__ f16 s_k_h[(size_t)BB * HW * CC];
__device__ f16 s_v_h[(size_t)BB * HW * CC];
__device__ f16 s_a_h[(size_t)BB * NQ * CC];
__device__ uint32_t s_mbits[(size_t)BB * NQ * HW / 32];

// ============================ helpers =======================================
__device__ __forceinline__ uint32_t smem_u32(const void* p) {
    uint32_t a;
    asm("{ .reg .u64 t; cvta.to.shared.u64 t, %1; cvt.u32.u64 %0, t; }"
        : "=r"(a) : "l"(p));
    return a;
}

__device__ __forceinline__ void ldx4(uint32_t* r, uint32_t addr) {
    asm volatile("ldmatrix.sync.aligned.m8n8.x4.shared.b16 {%0,%1,%2,%3}, [%4];"
                 : "=r"(r[0]), "=r"(r[1]), "=r"(r[2]), "=r"(r[3]) : "r"(addr));
}

__device__ __forceinline__ void ldx4t(uint32_t* r, uint32_t addr) {
    asm volatile("ldmatrix.sync.aligned.m8n8.x4.trans.shared.b16 {%0,%1,%2,%3}, [%4];"
                 : "=r"(r[0]), "=r"(r[1]), "=r"(r[2]), "=r"(r[3]) : "r"(addr));
}

__device__ __forceinline__ void mma_f16(float* c, const uint32_t* a,
                                        uint32_t b0, uint32_t b1) {
    asm volatile(
        "mma.sync.aligned.m16n8k16.row.col.f32.f16.f16.f32 "
        "{%0,%1,%2,%3}, {%4,%5,%6,%7}, {%8,%9}, {%0,%1,%2,%3};"
        : "+f"(c[0]), "+f"(c[1]), "+f"(c[2]), "+f"(c[3])
        : "r"(a[0]), "r"(a[1]), "r"(a[2]), "r"(a[3]), "r"(b0), "r"(b1));
}

__device__ __forceinline__ void cpa16(uint32_t dst, const void* src) {
    asm volatile("cp.async.cg.shared.global [%0], [%1], 16;"
                 :: "r"(dst), "l"(src) : "memory");
}
#define CP_COMMIT() asm volatile("cp.async.commit_group;" ::: "memory")
#define CP_WAIT0()  asm volatile("cp.async.wait_group 0;" ::: "memory")
#define CP_WAIT1()  asm volatile("cp.async.wait_group 1;" ::: "memory")

__device__ __forceinline__ uint32_t packh_hi(float x, float y) {
    __half2 h = __floats2half2_rn(x, y);
    return *(uint32_t*)&h;
}

__device__ __forceinline__ float ex2f(float x) {
    float y;
    asm("ex2.approx.ftz.f32 %0, %1;" : "=f"(y) : "f"(x));
    return y;
}

__device__ __forceinline__ uint32_t swz(int row, int chunk) {
    return (uint32_t)(row * 256 + ((chunk ^ (row & 7)) << 4));
}
__device__ __forceinline__ uint32_t swz128(int row, int chunk) {
    return (uint32_t)(row * 128 + ((chunk ^ (row & 7)) << 4));
}

// ============================================================================
// prep kernels (unchanged)
// ============================================================================
#define N4P_Q (BB * NQ * CC / 8)
#define N4P_M (BB * HW * CC / 8)
#define N4P_W (CC * CC / 8)
#define N4P_TOTAL (N4P_Q + N4P_M + 4 * N4P_W)

__global__ __launch_bounds__(256)
void round_all(const float* __restrict__ q,  f16* __restrict__ qo,
               const float* __restrict__ m,  f16* __restrict__ mo,
               const float* __restrict__ w0, f16* __restrict__ o0,
               const float* __restrict__ w1, f16* __restrict__ o1,
               const float* __restrict__ w2, f16* __restrict__ o2,
               const float* __restrict__ w3, f16* __restrict__ o3)
{
    size_t p = (size_t)blockIdx.x * blockDim.x + threadIdx.x;
    if (p >= (size_t)N4P_TOTAL) return;
    const float* x;
    f16* y;
    size_t off;
    if (p < N4P_Q) {
        x = q; y = qo; off = p;
    } else if (p < (size_t)N4P_Q + N4P_M) {
        x = m; y = mo; off = p - N4P_Q;
    } else {
        size_t r = p - N4P_Q - N4P_M;
        int ws = (int)(r / N4P_W);
        off = r % N4P_W;
        x = (ws == 0) ? w0 : (ws == 1) ? w1 : (ws == 2) ? w2 : w3;
        y = (ws == 0) ? o0 : (ws == 1) ? o1 : (ws == 2) ? o2 : o3;
    }
    const size_t i = off * 2;
    float4 v0 = ((const float4*)x)[i];
    float4 v1 = ((const float4*)x)[i + 1];
    __half2 a0 = __floats2half2_rn(v0.x, v0.y);
    __half2 a1 = __floats2half2_rn(v0.z, v0.w);
    __half2 a2 = __floats2half2_rn(v1.x, v1.y);
    __half2 a3 = __floats2half2_rn(v1.z, v1.w);
    ((uint4*)y)[off] = make_uint4(*(uint32_t*)&a0, *(uint32_t*)&a1,
                                  *(uint32_t*)&a2, *(uint32_t*)&a3);
}

__global__ __launch_bounds__(256)
void mask_bits(const float* __restrict__ m, uint32_t* __restrict__ out, int nwords)
{
    int w = blockIdx.x * blockDim.x + threadIdx.x;
    if (w >= nwords) return;
    const float4* p = (const float4*)(m + (size_t)w * 32);
    float4 v[8];
#pragma unroll
    for (int j = 0; j < 8; j++) v[j] = p[j];
    uint32_t bits = 0;
#pragma unroll
    for (int j = 0; j < 8; j++) {
        bits |= (v[j].x >= 0.5f ? (1u << (j * 4 + 0)) : 0u);
        bits |= (v[j].y >= 0.5f ? (1u << (j * 4 + 1)) : 0u);
        bits |= (v[j].z >= 0.5f ? (1u << (j * 4 + 2)) : 0u);
        bits |= (v[j].w >= 0.5f ? (1u << (j * 4 + 3)) : 0u);
    }
    out[w] = bits;
}

// ============================================================================
// GEMM core (R14 config: 512 threads, 16 warps 4x4, warp tile 32x32,
// BK=64, 3-stage cp.async, 2 CTAs/SM). Used by both fused-QKV and O-proj.
// ============================================================================
#define GSTG 32768
#define GEMM_SMEM (3 * GSTG)
#define GNS (CC / 64)

__device__ __forceinline__ void gemm_body(
    const f16* __restrict__ A, const f16* __restrict__ B,
    const float* __restrict__ bias, float* __restrict__ Yf,
    f16* __restrict__ Yh, float scale, int m0, int n0, char* sm)
{
    const uint32_t sb = smem_u32(sm);
    const int tid  = threadIdx.x;
    const int wid  = tid >> 5;
    const int lane = tid & 31;
    const int wm = wid & 3;
    const int wn = wid >> 2;

    const int lrow = tid >> 2;
    const int lcb  = (tid & 3) * 2;

    const f16* Ap = A + (size_t)(m0 + lrow) * CC;
    const f16* Bp = B + (size_t)(n0 + lrow) * CC;

    float acc[2][4][4];
#pragma unroll
    for (int i = 0; i < 2; i++)
#pragma unroll
        for (int j = 0; j < 4; j++)
#pragma unroll
            for (int k = 0; k < 4; k++) acc[i][j][k] = 0.f;

    const int krow_in = ((lane >> 4) & 1) * 8 + (lane & 7);
    const int kc      = (lane >> 3) & 1;
    const int arow    = wm * 32 + (lane & 15);
    const int ac      = lane >> 4;

    auto issue = [&](int s) {
        const uint32_t stb = sb + (uint32_t)((s % 3) * GSTG);
        const int ko = s * 64;
#pragma unroll
        for (int c = 0; c < 2; c++) {
            const int ch = lcb + c;
            const uint32_t so = swz128(lrow, ch);
            cpa16(stb + so,         Ap + ko + ch * 8);
            cpa16(stb + 16384 + so, Bp + ko + ch * 8);
        }
    };

    issue(0); CP_COMMIT();
    issue(1); CP_COMMIT();

    for (int s = 0; s < GNS; s++) {
        CP_WAIT1();
        __syncthreads();
        if (s + 2 < GNS) issue(s + 2);
        CP_COMMIT();

        const uint32_t stb = sb + (uint32_t)((s % 3) * GSTG);
#pragma unroll
        for (int kt = 0; kt < 4; kt++) {
            uint32_t a_[2][4];
#pragma unroll
            for (int mt = 0; mt < 2; mt++)
                ldx4(a_[mt], stb + swz128(arow + mt * 16, 2 * kt + ac));
            uint32_t b_[2][4];
#pragma unroll
            for (int nh = 0; nh < 2; nh++)
                ldx4(b_[nh], stb + 16384 +
                             swz128(wn * 32 + nh * 16 + krow_in, 2 * kt + kc));
#pragma unroll
            for (int mt = 0; mt < 2; mt++) {
#pragma unroll
                for (int nh = 0; nh < 2; nh++) {
                    mma_f16(acc[mt][2 * nh + 0], a_[mt], b_[nh][0], b_[nh][1]);
                    mma_f16(acc[mt][2 * nh + 1], a_[mt], b_[nh][2], b_[nh][3]);
                }
            }
        }
    }

#pragma unroll
    for (int mt = 0; mt < 2; mt++) {
        const int r0 = m0 + wm * 32 + mt * 16 + (lane >> 2);
#pragma unroll
        for (int nt = 0; nt < 4; nt++) {
            const int c = n0 + wn * 32 + nt * 8 + (lane & 3) * 2;
            float2 bv = *(const float2*)(bias + c);
            float y00 = acc[mt][nt][0] + bv.x;
            float y01 = acc[mt][nt][1] + bv.y;
            float y10 = acc[mt][nt][2] + bv.x;
            float y11 = acc[mt][nt][3] + bv.y;
            if (Yf) {
                *(float2*)(Yf + (size_t)r0 * CC + c)       = make_float2(y00, y01);
                *(float2*)(Yf + (size_t)(r0 + 8) * CC + c) = make_float2(y10, y11);
            } else {
                y00 *= scale; y01 *= scale; y10 *= scale; y11 *= scale;
                *(uint32_t*)(Yh + (size_t)r0 * CC + c)       = packh_hi(y00, y01);
                *(uint32_t*)(Yh + (size_t)(r0 + 8) * CC + c) = packh_hi(y10, y11);
            }
        }
    }
}

// Fused Q/K/V projections: blockIdx.z selects operand set; z=0 (Q) uses only
// the first 32 m-tiles, others early-exit. One launch = one CTA stream =
// merged wave tails.
__global__ __launch_bounds__(512, 2)
void gemm_qkv(const f16* __restrict__ Aq, const f16* __restrict__ Am,
              const f16* __restrict__ Bq, const f16* __restrict__ Bk,
              const f16* __restrict__ Bv,
              const float* __restrict__ bq, const float* __restrict__ bk,
              const float* __restrict__ bv,
              f16* __restrict__ Yq, f16* __restrict__ Yk, f16* __restrict__ Yv,
              float qscale)
{
    extern __shared__ char sm[];
    const int sel = blockIdx.z;
    if (sel == 0 && blockIdx.y >= (BB * NQ) / 128) return;
    const f16* A = (sel == 0) ? Aq : Am;
    const f16* B = (sel == 0) ? Bq : (sel == 1) ? Bk : Bv;
    const float* bias = (sel == 0) ? bq : (sel == 1) ? bk : bv;
    f16* Yh = (sel == 0) ? Yq : (sel == 1) ? Yk : Yv;
    const float scale = (sel == 0) ? qscale : 1.0f;
    gemm_body(A, B, bias, nullptr, Yh, scale,
              blockIdx.y * 128, blockIdx.x * 128, sm);
}

// O projection (fp32 out)
__global__ __launch_bounds__(512, 2)
void gemm_o(const f16* __restrict__ A, const f16* __restrict__ B,
            const float* __restrict__ bias, float* __restrict__ Yf)
{
    extern __shared__ char sm[];
    gemm_body(A, B, bias, Yf, nullptr, 1.0f,
              blockIdx.y * 128, blockIdx.x * 128, sm);
}

// ============================================================================
// Flash attention v7 (R14 exact revert): 2 CTAs/SM, resident Q smem,
// 2-stage KV ring, in-order softmax->PV, base-2 softmax, bitmask mask.
// ============================================================================
#define KVSTG 32768
#define QRGN  32768
#define FLASH_SMEM (QRGN + 2 * KVSTG)
#define NKV (HW / 64)

__global__ __launch_bounds__(256, 2)
void flash_attn_tc7(const f16* __restrict__ Qh,
                    const f16* __restrict__ Kh, const f16* __restrict__ Vh,
                    const uint32_t* __restrict__ Mb, f16* __restrict__ Oh)
{
    extern __shared__ char sm[];
    const uint32_t sb = smem_u32(sm);

    const int tid  = threadIdx.x;
    const int wid  = tid >> 5;
    const int lane = tid & 31;
    const int q0 = blockIdx.x * 128;
    const int h  = blockIdx.y;
    const int b  = blockIdx.z;

    {
        const int row = tid >> 1;
        const int cb  = (tid & 1) * 8;
        const f16* qsrc = Qh + (size_t)(b * NQ + q0 + row) * CC + h * DH;
#pragma unroll
        for (int c = 0; c < 8; c++) {
            const int ch = cb + c;
            cpa16(sb + swz(row, ch), qsrc + ch * 8);
        }
        CP_COMMIT();
    }

    const int qrow = 16 * wid + (lane & 15);
    const int qc   = lane >> 4;

    const int krow_in = ((lane >> 4) & 1) * 8 + (lane & 7);
    const int kc      = (lane >> 3) & 1;
    const int vrow_in = (lane & 7) + ((lane >> 3) & 1) * 8;
    const int vc      = lane >> 4;

    const int kvrow = tid >> 2;
    const int kvcb  = (tid & 3) * 4;

    const f16* khb = Kh + (size_t)(b * HW + kvrow) * CC + h * DH;
    const f16* vhb = Vh + (size_t)(b * HW + kvrow) * CC + h * DH;

    const int r0l = 16 * wid + (lane >> 2);
    const int mc0 = 2 * (lane & 3);
    const uint32_t* mrow0 = Mb + (size_t)(b * NQ + q0 + r0l) * (HW / 32);
    const uint32_t* mrow1 = mrow0 + (size_t)8 * (HW / 32);

    auto issue = [&](int i) {
        const uint32_t stb = sb + QRGN + (uint32_t)((i & 1) * KVSTG);
        const size_t koff = (size_t)(i * 64) * CC;
#pragma unroll
        for (int c = 0; c < 4; c++) {
            const int ch = kvcb + c;
            const uint32_t so = swz(kvrow, ch);
            cpa16(stb + so,         khb + koff + ch * 8);
            cpa16(stb + 16384 + so, vhb + koff + ch * 8);
        }
    };

    float m0r = -1e30f, m1r = -1e30f, l0r = 0.f, l1r = 0.f;
    float oc[16][4];
#pragma unroll
    for (int n = 0; n < 16; n++)
#pragma unroll
        for (int j = 0; j < 4; j++) oc[n][j] = 0.f;

    issue(0); CP_COMMIT();

    for (int i = 0; i < NKV; i++) {
        CP_WAIT0();
        __syncthreads();
        if (i + 1 < NKV) issue(i + 1);
        CP_COMMIT();

        const uint32_t stb = sb + QRGN + (uint32_t)((i & 1) * KVSTG);

        const uint2 w0 = *(const uint2*)(mrow0 + i * 2);
        const uint2 w1 = *(const uint2*)(mrow1 + i * 2);

        float sc[8][4];
#pragma unroll
        for (int n = 0; n < 8; n++)
#pragma unroll
            for (int j = 0; j < 4; j++) sc[n][j] = 0.f;

#pragma unroll
        for (int kt = 0; kt < 8; kt++) {
            uint32_t qh_[4];
            ldx4(qh_, sb + swz(qrow, 2 * kt + qc));
#pragma unroll
            for (int j = 0; j < 4; j++) {
                uint32_t kh_[4];
                ldx4(kh_, stb + swz(16 * j + krow_in, 2 * kt + kc));
                mma_f16(sc[2 * j + 0], qh_, kh_[0], kh_[1]);
                mma_f16(sc[2 * j + 1], qh_, kh_[2], kh_[3]);
            }
        }

        float mx0 = m0r, mx1 = m1r;
#pragma unroll
        for (int n = 0; n < 8; n++) {
            const uint32_t wa = (n < 4) ? w0.x : w0.y;
            const uint32_t wb = (n < 4) ? w1.x : w1.y;
            const int pos = (n & 3) * 8 + mc0;
            sc[n][0] = ((wa >> pos) & 1u)       ? sc[n][0] : -1e30f;
            sc[n][1] = ((wa >> (pos + 1)) & 1u) ? sc[n][1] : -1e30f;
            sc[n][2] = ((wb >> pos) & 1u)       ? sc[n][2] : -1e30f;
            sc[n][3] = ((wb >> (pos + 1)) & 1u) ? sc[n][3] : -1e30f;
            mx0 = fmaxf(mx0, fmaxf(sc[n][0], sc[n][1]));
            mx1 = fmaxf(mx1, fmaxf(sc[n][2], sc[n][3]));
        }
        mx0 = fmaxf(mx0, __shfl_xor_sync(0xffffffffu, mx0, 1));
        mx0 = fmaxf(mx0, __shfl_xor_sync(0xffffffffu, mx0, 2));
        mx1 = fmaxf(mx1, __shfl_xor_sync(0xffffffffu, mx1, 1));
        mx1 = fmaxf(mx1, __shfl_xor_sync(0xffffffffu, mx1, 2));

        const float alpha0 = ex2f(m0r - mx0);
        const float alpha1 = ex2f(m1r - mx1);
        m0r = mx0; m1r = mx1;

        float rs0 = 0.f, rs1 = 0.f;
#pragma unroll
        for (int n = 0; n < 8; n++) {
            sc[n][0] = ex2f(sc[n][0] - mx0);
            sc[n][1] = ex2f(sc[n][1] - mx0);
            sc[n][2] = ex2f(sc[n][2] - mx1);
            sc[n][3] = ex2f(sc[n][3] - mx1);
            rs0 += sc[n][0] + sc[n][1];
            rs1 += sc[n][2] + sc[n][3];
        }
        rs0 += __shfl_xor_sync(0xffffffffu, rs0, 1);
        rs0 += __shfl_xor_sync(0xffffffffu, rs0, 2);
        rs1 += __shfl_xor_sync(0xffffffffu, rs1, 1);
        rs1 += __shfl_xor_sync(0xffffffffu, rs1, 2);
        l0r = l0r * alpha0 + rs0;
        l1r = l1r * alpha1 + rs1;

        uint32_t pah[4][4];
#pragma unroll
        for (int kt = 0; kt < 4; kt++) {
            pah[kt][0] = packh_hi(sc[2 * kt][0],     sc[2 * kt][1]);
            pah[kt][1] = packh_hi(sc[2 * kt][2],     sc[2 * kt][3]);
            pah[kt][2] = packh_hi(sc[2 * kt + 1][0], sc[2 * kt + 1][1]);
            pah[kt][3] = packh_hi(sc[2 * kt + 1][2], sc[2 * kt + 1][3]);
        }
#pragma unroll
        for (int n = 0; n < 16; n++) {
            oc[n][0] *= alpha0; oc[n][1] *= alpha0;
            oc[n][2] *= alpha1; oc[n][3] *= alpha1;
        }

#pragma unroll
        for (int kt = 0; kt < 4; kt++) {
#pragma unroll
            for (int np = 0; np < 8; np++) {
                uint32_t v_[4];
                ldx4t(v_, stb + 16384 + swz(16 * kt + vrow_in, 2 * np + vc));
                mma_f16(oc[2 * np + 0], pah[kt], v_[0], v_[1]);
                mma_f16(oc[2 * np + 1], pah[kt], v_[2], v_[3]);
            }
        }
    }

    const float rl0 = 1.0f / l0r;
    const float rl1 = 1.0f / l1r;
    const size_t rbase0 = (size_t)(b * NQ + q0 + r0l) * CC + h * DH;
    const size_t rbase1 = rbase0 + (size_t)8 * CC;
#pragma unroll
    for (int n = 0; n < 16; n++) {
        const int c = n * 8 + mc0;
        *(uint32_t*)(Oh + rbase0 + c) = packh_hi(oc[n][0] * rl0, oc[n][1] * rl0);
        *(uint32_t*)(Oh + rbase1 + c) = packh_hi(oc[n][2] * rl1, oc[n][3] * rl1);
    }
}

// ---------------------------------------------------------------------------
extern "C" void kernel_launch(void* const* d_in, const int* in_sizes, int n_in,
                              void* d_out, int out_size)
{
    const float* query  = (const float*)d_in[0];
    const float* memory = (const float*)d_in[1];
    const float* mask   = (const float*)d_in[2];
    const float* Wq = (const float*)d_in[3];
    const float* bq = (const float*)d_in[4];
    const float* Wk = (const float*)d_in[5];
    const float* bk = (const float*)d_in[6];
    const float* Wv = (const float*)d_in[7];
    const float* bv = (const float*)d_in[8];
    const float* Wo = (const float*)d_in[9];
    const float* bo = (const float*)d_in[10];
    float* out = (float*)d_out;

    f16 *qin_h, *mem_h, *wq_h, *wk_h, *wv_h, *wo_h;
    f16 *q_h, *k_h, *v_h, *a_h;
    uint32_t* mb;
    cudaGetSymbolAddress((void**)&qin_h, s_qin_h);
    cudaGetSymbolAddress((void**)&mem_h, s_mem_h);
    cudaGetSymbolAddress((void**)&wq_h, s_wq_h);
    cudaGetSymbolAddress((void**)&wk_h, s_wk_h);
    cudaGetSymbolAddress((void**)&wv_h, s_wv_h);
    cudaGetSymbolAddress((void**)&wo_h, s_wo_h);
    cudaGetSymbolAddress((void**)&q_h, s_q_h);
    cudaGetSymbolAddress((void**)&k_h, s_k_h);
    cudaGetSymbolAddress((void**)&v_h, s_v_h);
    cudaGetSymbolAddress((void**)&a_h, s_a_h);
    cudaGetSymbolAddress((void**)&mb, s_mbits);

    cudaFuncSetAttribute(gemm_qkv,
                         cudaFuncAttributeMaxDynamicSharedMemorySize, GEMM_SMEM);
    cudaFuncSetAttribute(gemm_o,
                         cudaFuncAttributeMaxDynamicSharedMemorySize, GEMM_SMEM);
    cudaFuncSetAttribute(flash_attn_tc7,
                         cudaFuncAttributeMaxDynamicSharedMemorySize, FLASH_SMEM);

    static cudaStream_t s2 = nullptr;
    static cudaEvent_t ev_fork = nullptr, ev_join = nullptr;
    if (!s2) {
        cudaStreamCreateWithFlags(&s2, cudaStreamNonBlocking);
        cudaEventCreateWithFlags(&ev_fork, cudaEventDisableTiming);
        cudaEventCreateWithFlags(&ev_join, cudaEventDisableTiming);
    }

    dim3 blk(256);
    dim3 blk512(512);
    const float scale = 0.08838834764831845f * 1.4426950408889634f;

    // ---- fork: mask_bits on side stream ----
    cudaEventRecord(ev_fork, 0);
    cudaStreamWaitEvent(s2, ev_fork, 0);
    {
        const int nwords = BB * NQ * HW / 32;
        mask_bits<<<(nwords + 255) / 256, blk, 0, s2>>>(mask, mb, nwords);
    }
    cudaEventRecord(ev_join, s2);

    // ---- fused rounds ----
    round_all<<<(N4P_TOTAL + 255) / 256, blk>>>(
        query, qin_h, memory, mem_h,
        Wq, wq_h, Wk, wk_h, Wv, wv_h, Wo, wo_h);

    // ---- fused Q/K/V projections (single launch, merged tails) ----
    gemm_qkv<<<dim3(CC / 128, (BB * HW) / 128, 3), blk512, GEMM_SMEM>>>(
        qin_h, mem_h, wq_h, wk_h, wv_h, bq, bk, bv, q_h, k_h, v_h, scale);

    // ---- join: mask bitmap ready before flash ----
    cudaStreamWaitEvent(0, ev_join, 0);

    // ---- attention ----
    flash_attn_tc7<<<dim3(NQ / 128, HH, BB), blk, FLASH_SMEM>>>(
        q_h, k_h, v_h, mb, a_h);

    // ---- output projection ----
    gemm_o<<<dim3(CC / 128, (BB * NQ) / 128), blk512, GEMM_SMEM>>>(
        a_h, wo_h, bo, out);
}